// round 16
// baseline (speedup 1.0000x reference)
#include <cuda_runtime.h>

#define NQ     14
#define DEPTH  6
#define DIM    16384
#define NGATES (NQ * DEPTH)
#define NTHR   1024
#define NSLOT  16

typedef unsigned long long u64;

// Bank-conflict-free swizzle for the 4-bit register-slice layouts below:
// permute low 4 address bits by bits 4..7. Self-inverse, bijective.
// In every layout, addr mod 16 = (lane&15) ^ const within each 16-lane phase.
__device__ __forceinline__ int swz(int i) { return i ^ ((i >> 4) & 15); }

__device__ __forceinline__ u64 pk(float x, float y) {
    u64 r; asm("mov.b64 %0, {%1, %2};" : "=l"(r) : "f"(x), "f"(y)); return r;
}
__device__ __forceinline__ void upk(u64 v, float& x, float& y) {
    asm("mov.b64 {%0, %1}, %2;" : "=f"(x), "=f"(y) : "l"(v));
}

// RY butterfly on one complex pair, packed f32x2 (re,im rotated simultaneously).
__device__ __forceinline__ void rot(u64& a, u64& c, u64 ct2, u64 st2, u64 nst2) {
    u64 t0, t1, na, nc;
    asm("mul.rn.f32x2 %0, %1, %2;"     : "=l"(t0) : "l"(nst2), "l"(c));
    asm("mul.rn.f32x2 %0, %1, %2;"     : "=l"(t1) : "l"(st2),  "l"(a));
    asm("fma.rn.f32x2 %0, %1, %2, %3;" : "=l"(na) : "l"(ct2), "l"(a), "l"(t0));
    asm("fma.rn.f32x2 %0, %1, %2, %3;" : "=l"(nc) : "l"(ct2), "l"(c), "l"(t1));
    a = na; c = nc;
}

// Index maps (t: 10 bits, j: 4 bits). Register slot j covers:
// L0: index bits 0..3  (qubits 13..10)
// L1: index bits 4..7  (qubits 9..6)
// L2: index bits 8..11 (qubits 5..2)
// L3: index bits 10..13; gates only on bits 12..13 (qubits 1..0) via j bits 2..3
__device__ __forceinline__ int idxL0(int t, int j) { return (t << 4) | j; }
__device__ __forceinline__ int idxL1(int t, int j) {
    return (t & 15) | (j << 4) | ((t >> 4) << 8);
}
__device__ __forceinline__ int idxL2(int t, int j) {
    return (t & 255) | (j << 8) | ((t >> 8) << 12);
}
__device__ __forceinline__ int idxL3(int t, int j) { return t | (j << 10); }

// Apply gates on register-slot bits [BB0, BB0+NB): gate for slot-bit bb is
// theta index gbase + (QOF - bb)  (qubit = QOF - bb).
#define APPLY_SET(BB0, NB, QOF)                                         \
    _Pragma("unroll")                                                   \
    for (int bb = (BB0); bb < (BB0) + (NB); bb++) {                     \
        const int g = gbase + ((QOF) - bb);                             \
        const u64 ct2 = g_ct2[g], st2 = g_st2[g], nst2 = g_nst2[g];     \
        _Pragma("unroll")                                               \
        for (int j = 0; j < NSLOT; j++) {                               \
            if (j & (1 << bb)) continue;                                \
            rot(v[j], v[j | (1 << bb)], ct2, st2, nst2);                \
        }                                                               \
    }

#define APPLY_L0() APPLY_SET(0, 4, 13)
#define APPLY_L1() APPLY_SET(0, 4, 9)
#define APPLY_L2() APPLY_SET(0, 4, 5)
#define APPLY_L3() APPLY_SET(2, 2, 3)

// CZ chain diagonal: sign = (-1)^popc(i & (i>>1)), branchless sign-bit XOR.
#define APPLY_CZ(IDX)                                                   \
    _Pragma("unroll")                                                   \
    for (int j = 0; j < NSLOT; j++) {                                   \
        int i = IDX(t, j);                                              \
        u64 par = (u64)(__popc(i & (i >> 1)) & 1);                      \
        v[j] ^= (par << 63) | (par << 31);                              \
    }

#define LOAD_V(IDX)  _Pragma("unroll") for (int j = 0; j < NSLOT; j++) v[j] = state[swz(IDX(t, j))];
#define STORE_V(IDX) _Pragma("unroll") for (int j = 0; j < NSLOT; j++) state[swz(IDX(t, j))] = v[j];

__global__ void __launch_bounds__(NTHR, 1)
qsim_kernel(const float* __restrict__ x,      // (512, 14)
            const float* __restrict__ theta,  // (84,)
            const float* __restrict__ hw,     // (2, 14)
            const float* __restrict__ hb,     // (2,)
            float* __restrict__ out)          // (512, 2)
{
    extern __shared__ u64 state[];              // DIM packed complex amplitudes (swizzled)
    __shared__ u64 g_ct2[NGATES], g_st2[NGATES], g_nst2[NGATES];
    __shared__ float s_c[NQ], s_s[NQ];
    __shared__ float zacc[NQ];                  // z_p = sum pr*(1-2*bit_p)

    const int b = blockIdx.x;
    const int t = threadIdx.x;

    if (t < NGATES) {
        float h = 0.5f * theta[t];
        float ct = cosf(h), st = sinf(h);
        g_ct2[t] = pk(ct, ct); g_st2[t] = pk(st, st); g_nst2[t] = pk(-st, -st);
    }
    if (t < NQ) { float h = 0.5f * x[b * NQ + t]; s_c[t] = cosf(h); s_s[t] = sinf(h); zacc[t] = 0.0f; }
    __syncthreads();

    u64 v[NSLOT];

    // ===== pass 1: initial product state in layout L0, then L0(layer 0) =====
    // amp(i) = prod_q (bit_q ? sin(x_q/2) : cos(x_q/2)) * (-i)^popc(i); qubit q at bit NQ-1-q.
    // L0: i = (t<<4)|j -> bits 4..13 thread-uniform: factor once.
    {
        float tb = 1.0f;
        #pragma unroll
        for (int p = 4; p < NQ; p++)
            tb *= ((t >> (p - 4)) & 1) ? s_s[NQ - 1 - p] : s_c[NQ - 1 - p];
        const int pt = __popc(t);
        #pragma unroll
        for (int j = 0; j < NSLOT; j++) {
            float mag = tb;
            #pragma unroll
            for (int p = 0; p < 4; p++)
                mag *= ((j >> p) & 1) ? s_s[NQ - 1 - p] : s_c[NQ - 1 - p];
            int k = (pt + __popc(j)) & 3;   // (-i)^k: re=[1,0,-1,0], im=[0,-1,0,1]
            float re = (k == 0) ? mag : ((k == 2) ? -mag : 0.0f);
            float im = (k == 1) ? -mag : ((k == 3) ? mag : 0.0f);
            v[j] = pk(re, im);
        }
    }
    { const int gbase = 0; APPLY_L0(); }
    STORE_V(idxL0);
    __syncthreads();

    // ===== per layer pair: L1 | L2 | L3+CZ+L3 | L2 | L1 | L0+CZ[+L0] =====
    #pragma unroll 1
    for (int dp = 0; dp < DEPTH; dp += 2) {
        const int gb0 = dp * NQ;
        const int gb1 = gb0 + NQ;

        LOAD_V(idxL1);
        { const int gbase = gb0; APPLY_L1(); }
        STORE_V(idxL1);
        __syncthreads();

        LOAD_V(idxL2);
        { const int gbase = gb0; APPLY_L2(); }
        STORE_V(idxL2);
        __syncthreads();

        LOAD_V(idxL3);
        { const int gbase = gb0; APPLY_L3(); }
        APPLY_CZ(idxL3);
        { const int gbase = gb1; APPLY_L3(); }
        STORE_V(idxL3);
        __syncthreads();

        LOAD_V(idxL2);
        { const int gbase = gb1; APPLY_L2(); }
        STORE_V(idxL2);
        __syncthreads();

        LOAD_V(idxL1);
        { const int gbase = gb1; APPLY_L1(); }
        STORE_V(idxL1);
        __syncthreads();

        LOAD_V(idxL0);
        { const int gbase = gb1; APPLY_L0(); }
        APPLY_CZ(idxL0);
        if (dp + 2 < DEPTH) {
            const int gbase = gb1 + NQ;
            APPLY_L0();
            STORE_V(idxL0);
            __syncthreads();
        }
        // last iteration: v[] holds the final state in layout L0; no store needed.
    }

    // ---- probabilities -> signed per-bit sums z_p = sum pr*(1-2*bit_p), from registers ----
    // Final layout L0: i = (t<<4)|j.
    //   bits 0..3  <- j     : per-slot signed sums (zs[0..3])
    //   bits 4..8  <- t&31  : lane sign * tot (zs[4..8], built pre-reduction)
    //   bits 9..13 <- t>>5  : WARP-UNIFORM sign -> leader reconstructs from reduced tot.
    float zs[9];
    #pragma unroll
    for (int p = 0; p < 9; p++) zs[p] = 0.0f;
    float tot = 0.0f;
    #pragma unroll
    for (int j = 0; j < NSLOT; j++) {
        float re, im; upk(v[j], re, im);
        float pr = fmaf(re, re, im * im);
        tot += pr;
        #pragma unroll
        for (int p = 0; p < 4; p++)
            zs[p] += ((j >> p) & 1) ? -pr : pr;
    }
    #pragma unroll
    for (int p = 4; p < 9; p++)
        zs[p] = ((t >> (p - 4)) & 1) ? -tot : tot;

    #pragma unroll
    for (int o = 16; o; o >>= 1) {
        tot += __shfl_xor_sync(0xffffffffu, tot, o);
        #pragma unroll
        for (int p = 0; p < 9; p++)
            zs[p] += __shfl_xor_sync(0xffffffffu, zs[p], o);
    }
    if ((t & 31) == 0) {
        #pragma unroll
        for (int p = 0; p < 9; p++) atomicAdd(&zacc[p], zs[p]);
        #pragma unroll
        for (int p = 9; p < NQ; p++) {
            float zu = ((t >> (p - 4)) & 1) ? -tot : tot;   // t bits 5..9: warp-uniform
            atomicAdd(&zacc[p], zu);
        }
    }
    __syncthreads();

    // ---- head: out column p corresponds to bit position p (reference reverses qubit order) ----
    if (t < 2) {
        float lg = hb[t];
        #pragma unroll
        for (int p = 0; p < NQ; p++)
            lg = fmaf(zacc[p], hw[t * NQ + p], lg);
        out[b * 2 + t] = lg;
    }
}

extern "C" void kernel_launch(void* const* d_in, const int* in_sizes, int n_in,
                              void* d_out, int out_size)
{
    const float* x     = (const float*)d_in[0];
    const float* theta = (const float*)d_in[1];
    const float* hw    = (const float*)d_in[2];
    const float* hb    = (const float*)d_in[3];
    float* out = (float*)d_out;

    const int B = in_sizes[0] / NQ;            // 512
    const size_t smem = DIM * sizeof(u64);     // 128 KB dynamic

    cudaFuncSetAttribute(qsim_kernel, cudaFuncAttributeMaxDynamicSharedMemorySize, (int)smem);
    qsim_kernel<<<B, NTHR, smem>>>(x, theta, hw, hb, out);
}